// round 2
// baseline (speedup 1.0000x reference)
#include <cuda_runtime.h>
#include <stdint.h>

#define NNODES   100000
#define NGRAPHS  128
#define HDIM     256

// Scratch (no allocation allowed): per-node aggregated value
__device__ float d_agg[NNODES];

// ---------------------------------------------------------------------------
// Kernel 1: zero the aggregation buffer
// ---------------------------------------------------------------------------
__global__ void zero_kernel(int n) {
    int i = blockIdx.x * blockDim.x + threadIdx.x;
    if (i < n) d_agg[i] = 0.0f;
}

// ---------------------------------------------------------------------------
// Kernel 2: edge scatter-add.  agg[dst] += x[src] over all edges.
// edge_index layout: [2, E] row-major, int32 -> src at ei[0..E), dst at
// ei[E..2E).  4 edges per thread via int4 loads, RED.E.ADD.F32 scatter.
// ---------------------------------------------------------------------------
__global__ void edge_kernel(const int* __restrict__ ei,
                            const float* __restrict__ x,
                            int E) {
    int idx = blockIdx.x * blockDim.x + threadIdx.x;
    int i = idx << 2;                       // 4 edges per thread
    if (i + 3 < E) {
        int4 s = *reinterpret_cast<const int4*>(ei + i);
        int4 d = *reinterpret_cast<const int4*>(ei + E + i);
        float v0 = __ldg(&x[s.x]);
        float v1 = __ldg(&x[s.y]);
        float v2 = __ldg(&x[s.z]);
        float v3 = __ldg(&x[s.w]);
        atomicAdd(&d_agg[d.x], v0);
        atomicAdd(&d_agg[d.y], v1);
        atomicAdd(&d_agg[d.z], v2);
        atomicAdd(&d_agg[d.w], v3);
    } else if (i < E) {
        for (int e = i; e < E; e++) {
            atomicAdd(&d_agg[ei[E + e]], __ldg(&x[ei[e]]));
        }
    }
}

// ---------------------------------------------------------------------------
// Kernel 3: fused  h = relu(agg*W_l + b_l)  ->  mean-pool per graph
//                  -> out[g] = relu(pooled . W_out + b_out)
// batch is SORTED int32, so graph g's nodes are a contiguous range found by
// binary search. One block (256 threads, one thread per feature) per graph.
// ---------------------------------------------------------------------------
__global__ __launch_bounds__(HDIM)
void pool_kernel(const int* __restrict__ batch,
                 const float* __restrict__ W_l,
                 const float* __restrict__ b_l,
                 const float* __restrict__ W_out,
                 const float* __restrict__ b_out,
                 float* __restrict__ out,
                 int N) {
    const int g = blockIdx.x;
    const int t = threadIdx.x;

    // lower_bound(batch, g) and lower_bound(batch, g+1) — identical across
    // the block, loads broadcast from L1/L2.
    int lo = 0, hi = N;
    while (lo < hi) { int m = (lo + hi) >> 1; if (batch[m] < g) lo = m + 1; else hi = m; }
    const int start = lo;
    hi = N;
    while (lo < hi) { int m = (lo + hi) >> 1; if (batch[m] < g + 1) lo = m + 1; else hi = m; }
    const int end = lo;

    const float w = W_l[t];
    const float b = b_l[t];
    float s = 0.0f;

    __shared__ float sa[HDIM];
    for (int base = start; base < end; base += HDIM) {
        int n = min(HDIM, end - base);
        __syncthreads();
        if (t < n) sa[t] = d_agg[base + t];
        __syncthreads();
        int j = 0;
        for (; j + 3 < n; j += 4) {
            s += fmaxf(fmaf(sa[j],     w, b), 0.0f);
            s += fmaxf(fmaf(sa[j + 1], w, b), 0.0f);
            s += fmaxf(fmaf(sa[j + 2], w, b), 0.0f);
            s += fmaxf(fmaf(sa[j + 3], w, b), 0.0f);
        }
        for (; j < n; j++)
            s += fmaxf(fmaf(sa[j], w, b), 0.0f);
    }

    const float cnt = fmaxf((float)(end - start), 1.0f);
    float val = (s / cnt) * W_out[t];

    // block-wide sum over the 256 features
    __shared__ float red[HDIM];
    red[t] = val;
    __syncthreads();
    for (int off = HDIM >> 1; off > 0; off >>= 1) {
        if (t < off) red[t] += red[t + off];
        __syncthreads();
    }
    if (t == 0)
        out[g] = fmaxf(red[0] + b_out[0], 0.0f);
}

// ---------------------------------------------------------------------------
// Launch
// inputs (metadata order):
//   0: x       float32 [N]      (N,1)
//   1: ei      int32   [2*E]    (JAX x64 disabled -> int64 request => int32)
//   2: batch   int32   [N]
//   3: W_l     float32 [256]
//   4: b_l     float32 [256]
//   5: W_out   float32 [256]
//   6: b_out   float32 [1]
// out: float32 [128]
// ---------------------------------------------------------------------------
extern "C" void kernel_launch(void* const* d_in, const int* in_sizes, int n_in,
                              void* d_out, int out_size) {
    const float* x     = (const float*)d_in[0];
    const int*   ei    = (const int*)d_in[1];
    const int*   batch = (const int*)d_in[2];
    const float* W_l   = (const float*)d_in[3];
    const float* b_l   = (const float*)d_in[4];
    const float* W_out = (const float*)d_in[5];
    const float* b_out = (const float*)d_in[6];
    float*       out   = (float*)d_out;

    const int N = in_sizes[0];
    const int E = in_sizes[1] / 2;

    {
        int threads = 256;
        int blocks = (N + threads - 1) / threads;
        zero_kernel<<<blocks, threads>>>(N);
    }
    {
        int threads = 256;
        int workers = (E + 3) / 4;
        int blocks = (workers + threads - 1) / threads;
        edge_kernel<<<blocks, threads>>>(ei, x, E);
    }
    {
        pool_kernel<<<NGRAPHS, HDIM>>>(batch, W_l, b_l, W_out, b_out, out, N);
    }
}

// round 3
// speedup vs baseline: 1.4437x; 1.4437x over previous
#include <cuda_runtime.h>
#include <stdint.h>

#define NNODES   100000
#define NGRAPHS  128
#define HDIM     256

// Scratch (no allocation allowed)
__device__ float d_agg[NNODES];
__device__ int   d_starts[NGRAPHS + 1];

// ---------------------------------------------------------------------------
// Boundary detection: batch is sorted int32; d_starts[g] = lower_bound(batch,g),
// d_starts[NGRAPHS] = N.  One coalesced pass, no binary search.
// ---------------------------------------------------------------------------
__global__ void boundary_kernel(const int* __restrict__ batch, int N) {
    int i = blockIdx.x * blockDim.x + threadIdx.x;
    if (i >= N) return;
    int b    = batch[i];
    int prev = (i == 0) ? -1 : batch[i - 1];
    for (int g = prev + 1; g <= b; g++) d_starts[g] = i;
    if (i == N - 1)
        for (int g = b + 1; g <= NGRAPHS; g++) d_starts[g] = N;
}

// ---------------------------------------------------------------------------
// Edge scatter-add: agg[dst] += x[src].  8 edges/thread, front-batched
// int4 index loads (4x LDG.128), then 8 gathers, then 8 REDs.
// ---------------------------------------------------------------------------
__global__ void edge_kernel(const int* __restrict__ ei,
                            const float* __restrict__ x,
                            int E) {
    int t = blockIdx.x * blockDim.x + threadIdx.x;
    int i = t << 3;
    if (i + 7 < E) {
        const int4* sp = reinterpret_cast<const int4*>(ei + i);
        const int4* dp = reinterpret_cast<const int4*>(ei + E + i);
        int4 s0 = __ldg(sp);
        int4 s1 = __ldg(sp + 1);
        int4 d0 = __ldg(dp);
        int4 d1 = __ldg(dp + 1);
        float v0 = __ldg(x + s0.x);
        float v1 = __ldg(x + s0.y);
        float v2 = __ldg(x + s0.z);
        float v3 = __ldg(x + s0.w);
        float v4 = __ldg(x + s1.x);
        float v5 = __ldg(x + s1.y);
        float v6 = __ldg(x + s1.z);
        float v7 = __ldg(x + s1.w);
        atomicAdd(&d_agg[d0.x], v0);
        atomicAdd(&d_agg[d0.y], v1);
        atomicAdd(&d_agg[d0.z], v2);
        atomicAdd(&d_agg[d0.w], v3);
        atomicAdd(&d_agg[d1.x], v4);
        atomicAdd(&d_agg[d1.y], v5);
        atomicAdd(&d_agg[d1.z], v6);
        atomicAdd(&d_agg[d1.w], v7);
    } else if (i < E) {
        for (int e = i; e < E; e++)
            atomicAdd(&d_agg[ei[E + e]], __ldg(x + ei[e]));
    }
}

// ---------------------------------------------------------------------------
// Fused  relu(agg*W_l + b_l) -> mean pool -> relu(pooled.W_out + b_out).
// One block per graph, 512 threads = 2 halves x 256 features.
// Each half processes half the node range; shuffle-tree reduces 512 partials.
// ---------------------------------------------------------------------------
__global__ __launch_bounds__(512)
void pool_kernel(const float* __restrict__ W_l,
                 const float* __restrict__ b_l,
                 const float* __restrict__ W_out,
                 const float* __restrict__ b_out,
                 float* __restrict__ out) {
    const int g = blockIdx.x;
    const int t = threadIdx.x;
    const int k = t & 255;     // feature
    const int h = t >> 8;      // half id

    const int start = d_starts[g];
    const int end   = d_starts[g + 1];
    const int len   = end - start;
    const int half0 = (len + 1) >> 1;                  // size of half 0 (>= half 1)
    const int s0    = start + h * half0;
    const int myLen = h ? (len - half0) : half0;
    const int nt    = (half0 + 255) >> 8;              // tile count (uniform across block)

    const float w = W_l[k];
    const float b = b_l[k];
    float acc = 0.0f;

    __shared__ float sa[2][HDIM];
    for (int it = 0; it < nt; it++) {
        const int base = it << 8;
        const int n = min(HDIM, myLen - base);         // may be <= 0 for half 1
        __syncthreads();
        if (k < n) sa[h][k] = d_agg[s0 + base + k];
        __syncthreads();
        const int n4 = n >> 2;                          // n<=0 -> no iterations
        const float4* sv = reinterpret_cast<const float4*>(sa[h]);
        for (int j = 0; j < n4; j++) {
            float4 v = sv[j];                           // warp-broadcast LDS.128
            acc += fmaxf(fmaf(v.x, w, b), 0.0f);
            acc += fmaxf(fmaf(v.y, w, b), 0.0f);
            acc += fmaxf(fmaf(v.z, w, b), 0.0f);
            acc += fmaxf(fmaf(v.w, w, b), 0.0f);
        }
        for (int j = n4 << 2; j < n; j++)
            acc += fmaxf(fmaf(sa[h][j], w, b), 0.0f);
    }

    const float cnt = fmaxf((float)len, 1.0f);
    float val = acc * W_out[k] / cnt;

    // reduce 512 partials: warp shuffle + smem tree
    #pragma unroll
    for (int off = 16; off; off >>= 1)
        val += __shfl_xor_sync(0xffffffffu, val, off);
    __shared__ float warpsum[16];
    const int wid = t >> 5, lid = t & 31;
    if (lid == 0) warpsum[wid] = val;
    __syncthreads();
    if (wid == 0) {
        float v = (lid < 16) ? warpsum[lid] : 0.0f;
        #pragma unroll
        for (int off = 8; off; off >>= 1)
            v += __shfl_xor_sync(0xffffffffu, v, off);
        if (lid == 0) out[g] = fmaxf(v + b_out[0], 0.0f);
    }
}

// ---------------------------------------------------------------------------
// inputs (metadata order):
//   0: x float32[N]  1: ei int32[2E]  2: batch int32[N]
//   3: W_l f32[256]  4: b_l f32[256]  5: W_out f32[256]  6: b_out f32[1]
// out: float32 [128]
// ---------------------------------------------------------------------------
extern "C" void kernel_launch(void* const* d_in, const int* in_sizes, int n_in,
                              void* d_out, int out_size) {
    const float* x     = (const float*)d_in[0];
    const int*   ei    = (const int*)d_in[1];
    const int*   batch = (const int*)d_in[2];
    const float* W_l   = (const float*)d_in[3];
    const float* b_l   = (const float*)d_in[4];
    const float* W_out = (const float*)d_in[5];
    const float* b_out = (const float*)d_in[6];
    float*       out   = (float*)d_out;

    const int N = in_sizes[0];
    const int E = in_sizes[1] / 2;

    // zero agg via memset node (no kernel launch cost)
    void* aggp = nullptr;
    cudaGetSymbolAddress(&aggp, d_agg);
    cudaMemsetAsync(aggp, 0, (size_t)N * sizeof(float), 0);

    {
        int threads = 256;
        int blocks = (N + threads - 1) / threads;
        boundary_kernel<<<blocks, threads>>>(batch, N);
    }
    {
        int threads = 256;
        int workers = (E + 7) / 8;
        int blocks = (workers + threads - 1) / threads;
        edge_kernel<<<blocks, threads>>>(ei, x, E);
    }
    {
        pool_kernel<<<NGRAPHS, 512>>>(W_l, b_l, W_out, b_out, out);
    }
}